// round 12
// baseline (speedup 1.0000x reference)
#include <cuda_runtime.h>

#define B  32
#define L  1024
#define D  512
#define NN 512

// 8 partial-sum planes of sum_l(i - j) over L-eighths: [8][B][D]
__device__ float g_part[8 * B * D];
// reduced mean-diff md[b][d]
__device__ float g_md[B * D];
// grid-barrier ticket counter (zero-initialized; epoch math => replay-safe)
__device__ unsigned int g_bar;
// DCE-defeating sink for the W prefetch
__device__ float g_sink;

// ---------------------------------------------------------------------------
// Kernel 1 (unchanged — measured ~22.9us, ~5.6 TB/s):
// part[lo][b][d] = sum_{l in eighth lo} (i[b,l,d] - j[b,l,d])
// 1024 blocks x 256 thr, all resident. Full-warp 512B LDG.128 rows, __ldcs
// streaming so W stays in L2. Side job: prefetch W (1 MB) into L2.
// ---------------------------------------------------------------------------
__global__ void __launch_bounds__(256, 8) mean_diff_kernel(
    const float* __restrict__ gi, const float* __restrict__ gj,
    const float* __restrict__ W)
{
    const int blk = blockIdx.x;
    const int b   = blk >> 5;
    const int r   = blk & 31;
    const int dt  = r >> 3;           // 128-float d tile (4 per D)
    const int lo  = r & 7;            // L eighth
    const int tid = threadIdx.x;
    const int dq  = tid & 31;
    const int lg  = tid >> 5;

    if (tid < 64) {
        float4 w = __ldcg(((const float4*)W) + blk * 64 + tid);
        float t = w.x + w.y + w.z + w.w;
        if (__float_as_int(t) == 0x7f800001)  // never true in practice
            g_sink = t;
    }

    const int rowq = D / 4;
    const float4* pi = (const float4*)(gi + (size_t)b * L * D) + dt * 32 + dq;
    const float4* pj = (const float4*)(gj + (size_t)b * L * D) + dt * 32 + dq;

    const int l0 = lo * 128 + lg * 16;
    float4 acc = make_float4(0.f, 0.f, 0.f, 0.f);
    #pragma unroll
    for (int rr = 0; rr < 16; rr++) {
        size_t off = (size_t)(l0 + rr) * rowq;
        float4 a = __ldcs(pi + off);
        float4 c = __ldcs(pj + off);
        acc.x += a.x - c.x;
        acc.y += a.y - c.y;
        acc.z += a.z - c.z;
        acc.w += a.w - c.w;
    }

    __shared__ float4 s[256];
    s[tid] = acc;
    __syncthreads();

    #pragma unroll
    for (int stride = 128; stride >= 32; stride >>= 1) {
        if (tid < stride) {
            float4 o = s[tid + stride];
            s[tid].x += o.x; s[tid].y += o.y; s[tid].z += o.z; s[tid].w += o.w;
        }
        __syncthreads();
    }

    if (tid < 32)
        ((float4*)(g_part + lo * B * D + b * D + dt * 128))[tid] = s[tid];
}

// ---------------------------------------------------------------------------
// Kernel 2: two phases separated by an in-kernel grid barrier.
// Grid: 128 blocks x 512 threads (one wave; 128 <= 148 SMs -> all blocks
// resident simultaneously, so the spin barrier cannot deadlock).
//
// Phase A: cooperative plane reduction: md[b][d] = (1/L)*sum_pl part[pl][b][d]
//          block blk handles flat indices [blk*128, blk*128+128). 512KB reads
//          total (was 8-16MB when done redundantly per tile).
// Barrier: ticketed atomic counter; target = (ticket/128+1)*128, so repeated
//          graph replays work without ever resetting the counter.
// Phase B: tile = 8 batches x 16 n-cols x all 512 d. bg = blk>>5, nt = blk&31.
//          smd[8][512] staged once (coalesced float4), each W element loaded
//          once and reused in 8 FMAs -> W L2 traffic 4MB total.
//          nloc = tid&15, dg = tid>>4 (32 d-groups of 16): 16 independent
//          scalar W loads per thread, then 32-way smem reduction.
// ---------------------------------------------------------------------------
__global__ void __launch_bounds__(512) gemv_combine_kernel(
    const float* __restrict__ W, const float* __restrict__ bias,
    float* __restrict__ out)
{
    const int blk = blockIdx.x;
    const int tid = threadIdx.x;

    // ---- Phase A: plane reduction into g_md ----
    if (tid < 128) {
        const int idx = blk * 128 + tid;        // idx = b*D + d
        float v = 0.f;
        #pragma unroll
        for (int pl = 0; pl < 8; pl++)
            v += g_part[pl * B * D + idx];
        g_md[idx] = v * (1.0f / (float)L);
    }

    // ---- Grid barrier (replay-safe epoch ticket) ----
    __threadfence();
    __syncthreads();
    if (tid == 0) {
        unsigned int ticket = atomicAdd(&g_bar, 1u);
        unsigned int target = (ticket / 128u + 1u) * 128u;
        while (*(volatile unsigned int*)&g_bar < target) { }
        __threadfence();
    }
    __syncthreads();

    // ---- Phase B: GEMV tile with 8-batch W reuse ----
    const int bg = blk >> 5;          // 4 batch groups of 8
    const int nt = blk & 31;          // 16-wide n tile
    const int b0 = bg * 8;

    __shared__ float smd[8][D];       // md for 8 batches (16 KB)
    {
        float4* s4 = (float4*)&smd[0][0];
        const float4* g4 = (const float4*)(g_md + b0 * D);
        s4[tid]       = g4[tid];          // 1024 float4 total
        s4[tid + 512] = g4[tid + 512];
    }
    __syncthreads();

    const int nloc = tid & 15;
    const int dg   = tid >> 4;        // 32 d-groups of 16
    const int n    = nt * 16 + nloc;
    const float* Wp = W + (size_t)(dg * 16) * NN + n;

    float u[8];
    #pragma unroll
    for (int bb = 0; bb < 8; bb++) u[bb] = 0.f;

    #pragma unroll
    for (int d = 0; d < 16; d++) {
        float w = __ldg(Wp + (size_t)d * NN);
        const int di = dg * 16 + d;
        #pragma unroll
        for (int bb = 0; bb < 8; bb++)
            u[bb] = fmaf(smd[bb][di], w, u[bb]);
    }

    __shared__ float su[8][512];      // 16 KB
    #pragma unroll
    for (int bb = 0; bb < 8; bb++)
        su[bb][tid] = u[bb];
    __syncthreads();

    // 128 outputs (8 batches x 16 n), each a 32-way partial sum.
    if (tid < 128) {
        const int bb = tid >> 4;
        const int nn = tid & 15;
        float t = 0.f;
        #pragma unroll
        for (int g = 0; g < 32; g++)
            t += su[bb][g * 16 + nn];
        float bv = bias[nt * 16 + nn];
        out[(b0 + bb) * NN + nt * 16 + nn] =
            0.5f * (fmaxf(t + bv, 0.f) + fmaxf(bv - t, 0.f));
    }
}

extern "C" void kernel_launch(void* const* d_in, const int* in_sizes, int n_in,
                              void* d_out, int out_size)
{
    const float* gi   = (const float*)d_in[0];   // i     [B, L, D]
    const float* gj   = (const float*)d_in[1];   // j     [B, L, D]
    const float* W    = (const float*)d_in[2];   // W_agg [D, NN]
    const float* bias = (const float*)d_in[3];   // b_agg [NN]
    float* out = (float*)d_out;                  // [B, NN]

    mean_diff_kernel<<<1024, 256>>>(gi, gj, W);
    gemv_combine_kernel<<<128, 512>>>(W, bias, out);
}